// round 6
// baseline (speedup 1.0000x reference)
#include <cuda_runtime.h>
#include <math.h>

// ---------------------------------------------------------------------------
// Matern kernel matrix via tabulated L(x) = log2(C * x^nu * K_nu(x)).
// Kernel 1 builds a 1025-entry table over x in [0,96] (48-pt trapezoid of the
// reference's integral representation, spectrally converged).
// Kernel 2: full 16x16 grid of 64x64 tiles (no mirror pass -- parallelism
// beats the 2x FMA savings), 256 threads, 4x4 register micro-tile, smem table.
// ---------------------------------------------------------------------------

#define TBL_N    1024
#define TBL_XMAX 96.0f
#define TBL_DX   (TBL_XMAX / TBL_N)
#define TBL_INVDX ((float)TBL_N / TBL_XMAX)

#define NQT 48
#define HQT (6.0f / (NQT - 1))
#define LOG2E 1.44269504088896340736f

__device__ float2 g_tbl[TBL_N + 2];   // {L_k, L_{k+1}}
__device__ float  g_fac;              // sqrt(2 nu) / lengthscale
__device__ float  g_var;              // variance

__device__ __forceinline__ float ex2f(float x) {
    float r; asm("ex2.approx.ftz.f32 %0, %1;" : "=f"(r) : "f"(x)); return r;
}
__device__ __forceinline__ float lg2f(float x) {
    float r; asm("lg2.approx.f32 %0, %1;" : "=f"(r) : "f"(x)); return r;
}

// --- kernel 1: table build (8 lanes per entry, 32 entries per block) --------
__global__ __launch_bounds__(256) void build_table(const float* __restrict__ nu_p,
                                                   const float* __restrict__ lv_p,
                                                   const float* __restrict__ ll_p) {
    __shared__ float s_log2C, s_nu;
    if (threadIdx.x == 0) {
        float nu = nu_p[0];
        s_nu = nu;
        s_log2C = lv_p[0] * LOG2E + (1.f - nu) - lgammaf(nu) * LOG2E;
        if (blockIdx.x == 0) {
            g_fac = sqrtf(2.f * nu) * __expf(-ll_p[0]);
            g_var = __expf(lv_p[0]);
        }
    }
    __syncthreads();

    const float nu = s_nu;
    const int k    = blockIdx.x * 32 + (threadIdx.x >> 3);
    const int lane = threadIdx.x & 7;
    const float x  = TBL_DX * (float)k;

    float S = 0.f;
#pragma unroll
    for (int m = 0; m < 6; m++) {
        int q   = lane + 8 * m;
        float t = HQT * (float)q;
        float w = (q == 0 || q == NQT - 1) ? 0.5f * HQT : HQT;
        float a = (coshf(t) - 1.f) * LOG2E;
        S += (w * coshf(nu * t)) * ex2f(-x * a);
    }
    S += __shfl_xor_sync(0xffffffffu, S, 1);
    S += __shfl_xor_sync(0xffffffffu, S, 2);
    S += __shfl_xor_sync(0xffffffffu, S, 4);

    if (lane == 0 && k <= TBL_N) {
        float L = s_log2C + nu * lg2f(x) - x * LOG2E + lg2f(S);
        L = fmaxf(L, -150.f);
        g_tbl[k].x = L;
        if (k > 0) g_tbl[k - 1].y = L;
    }
}

// --- kernel 2: full grid, 64x64 tiles, 4x4 micro-tile ------------------------
__global__ __launch_bounds__(256) void matern_main(const float* __restrict__ X,
                                                   float* __restrict__ out,
                                                   int N) {
    __shared__ float  sxi[64][36];     // stride multiple of 4 floats (16B)
    __shared__ float  sxj[64][36];
    __shared__ float  sni[64], snj[64];
    __shared__ float2 stbl[TBL_N + 1];
    __shared__ float  sfac, svar;

    const int tid = threadIdx.x;
    const int tx = tid & 15, ty = tid >> 4;

    const int i0 = blockIdx.y * 64, j0 = blockIdx.x * 64;

    // table copy first (overlaps with tile loads below)
    {
        const float2* gt = g_tbl;
#pragma unroll
        for (int m = 0; m < 4; m++) {
            int idx = m * 256 + tid;
            if (idx <= TBL_N) stbl[idx] = gt[idx];
        }
    }
    // tile loads: 512 float4 per tile, 2 per thread
    {
        const float4* Xi = (const float4*)(X + i0 * 32);
        const float4* Xj = (const float4*)(X + j0 * 32);
#pragma unroll
        for (int m = 0; m < 2; m++) {
            int idx = m * 256 + tid;          // 0..511
            int r = idx >> 3, k = idx & 7;
            *(float4*)&sxi[r][4 * k] = Xi[idx];
            *(float4*)&sxj[r][4 * k] = Xj[idx];
        }
    }
    if (tid == 0) { sfac = g_fac; svar = g_var; }
    __syncthreads();

    // row norms
    if (tid < 128) {
        int r = tid & 63;
        const float* row = (tid < 64) ? sxi[r] : sxj[r];
        float s = 0.f;
#pragma unroll
        for (int k = 0; k < 32; k++) s = fmaf(row[k], row[k], s);
        if (tid < 64) sni[r] = s; else snj[r] = s;
    }
    __syncthreads();

    // 4x4 register micro-tile dot products
    float acc[4][4];
#pragma unroll
    for (int r = 0; r < 4; r++)
#pragma unroll
        for (int c = 0; c < 4; c++) acc[r][c] = 0.f;

#pragma unroll
    for (int kc = 0; kc < 8; kc++) {
        float4 a[4], b[4];
#pragma unroll
        for (int r = 0; r < 4; r++) a[r] = *(const float4*)&sxi[ty * 4 + r][kc * 4];
#pragma unroll
        for (int c = 0; c < 4; c++) b[c] = *(const float4*)&sxj[tx * 4 + c][kc * 4];
#pragma unroll
        for (int r = 0; r < 4; r++)
#pragma unroll
            for (int c = 0; c < 4; c++) {
                acc[r][c] = fmaf(a[r].x, b[c].x, acc[r][c]);
                acc[r][c] = fmaf(a[r].y, b[c].y, acc[r][c]);
                acc[r][c] = fmaf(a[r].z, b[c].z, acc[r][c]);
                acc[r][c] = fmaf(a[r].w, b[c].w, acc[r][c]);
            }
    }

    const float fac = sfac, var_s = svar;
    float ni[4], nj[4];
#pragma unroll
    for (int r = 0; r < 4; r++) ni[r] = sni[ty * 4 + r];
#pragma unroll
    for (int c = 0; c < 4; c++) nj[c] = snj[tx * 4 + c];

    const int i_base = i0 + ty * 4, j_base = j0 + tx * 4;

#pragma unroll
    for (int r = 0; r < 4; r++) {
        float4 v;
#pragma unroll
        for (int c = 0; c < 4; c++) {
            float sq = fmaxf(fmaf(-2.f, acc[r][c], ni[r] + nj[c]), 1e-24f);
            float x  = fmaxf(fac * sqrtf(sq), 1e-10f);
            float u  = fminf(x * TBL_INVDX, (float)TBL_N - 0.001f);
            int   kk = (int)u;
            float f  = u - (float)kk;
            float2 Lp = stbl[kk];
            float val = ex2f(fmaf(f, Lp.y - Lp.x, Lp.x));
            if (i_base + r == j_base + c) val = var_s;
            ((float*)&v)[c] = val;
        }
        *(float4*)&out[(i_base + r) * N + j_base] = v;
    }
}

extern "C" void kernel_launch(void* const* d_in, const int* in_sizes, int n_in,
                              void* d_out, int out_size) {
    const float* X  = (const float*)d_in[0];
    const float* nu = (const float*)d_in[1];
    const float* lv = (const float*)d_in[2];
    const float* ll = (const float*)d_in[3];
    float* out = (float*)d_out;
    const int N = in_sizes[0] / 32;   // 1024

    build_table<<<(TBL_N + 1 + 31) / 32, 256>>>(nu, lv, ll);

    dim3 grid(N / 64, N / 64), block(256);
    matern_main<<<grid, block>>>(X, out, N);
}